// round 1
// baseline (speedup 1.0000x reference)
#include <cuda_runtime.h>

#define BB 4
#define C1 256
#define MID 64
#define HW 56
#define PP 3136       // 56*56
#define W2O 784       // 49*16
#define KS 7
#define NG 16
#define GCH 16
#define BN_EPS 1e-3f

// Scratch intermediates (allocation-free: __device__ globals)
__device__ float g_y[BB * MID * PP];     // 3.2 MB
__device__ float g_wt[BB * W2O * PP];    // 39.3 MB

// ---------------------------------------------------------------------------
// Kernel 1: y[b,m,p] = ACON(BN1( sum_c x[b,c,p] * w1[m,c] ))
// Tile: 64 m (all) x 64 px per block, 256 threads, 4x4 register tile/thread.
// ---------------------------------------------------------------------------
__global__ __launch_bounds__(256) void k1_conv1_bn_acon(
    const float* __restrict__ x, const float* __restrict__ w1,
    const float* __restrict__ g1, const float* __restrict__ b1,
    const float* __restrict__ mu1, const float* __restrict__ v1,
    const float* __restrict__ ap1, const float* __restrict__ ap2,
    const float* __restrict__ ab)
{
    __shared__ float ws[16][68];   // [k][m], padded
    __shared__ float xs[16][64];   // [k][px]

    const int tid = threadIdx.x;
    const int b   = blockIdx.y;
    const int p0  = blockIdx.x * 64;
    const int tm  = tid & 15;      // m-tile group  -> m0 = tm*4
    const int tp  = tid >> 4;      // px-tile group -> px0 = tp*4

    float acc[4][4] = {};
    const float* xb = x + (size_t)b * C1 * PP + p0;

    for (int k0 = 0; k0 < C1; k0 += 16) {
        // stage w1 chunk: ws[k][m] = w1[m*C1 + k0 + k]
        {
            const int c  = tid & 15;
            const int mb = tid >> 4;
            #pragma unroll
            for (int it = 0; it < 4; ++it) {
                const int m = mb + 16 * it;
                ws[c][m] = w1[m * C1 + k0 + c];
            }
            const int px = tid & 63;
            const int kb = tid >> 6;
            #pragma unroll
            for (int it = 0; it < 4; ++it) {
                const int k = kb + 4 * it;
                xs[k][px] = xb[(k0 + k) * PP + px];
            }
        }
        __syncthreads();
        #pragma unroll
        for (int k = 0; k < 16; ++k) {
            const float4 wv = *(const float4*)&ws[k][tm * 4];
            const float4 xv = *(const float4*)&xs[k][tp * 4];
            acc[0][0] += wv.x * xv.x; acc[0][1] += wv.x * xv.y;
            acc[0][2] += wv.x * xv.z; acc[0][3] += wv.x * xv.w;
            acc[1][0] += wv.y * xv.x; acc[1][1] += wv.y * xv.y;
            acc[1][2] += wv.y * xv.z; acc[1][3] += wv.y * xv.w;
            acc[2][0] += wv.z * xv.x; acc[2][1] += wv.z * xv.y;
            acc[2][2] += wv.z * xv.z; acc[2][3] += wv.z * xv.w;
            acc[3][0] += wv.w * xv.x; acc[3][1] += wv.w * xv.y;
            acc[3][2] += wv.w * xv.z; acc[3][3] += wv.w * xv.w;
        }
        __syncthreads();
    }

    // Epilogue: BN1 + ACON-C, vectorized store
    #pragma unroll
    for (int i = 0; i < 4; ++i) {
        const int m = tm * 4 + i;
        const float s  = g1[m] * rsqrtf(v1[m] + BN_EPS);
        const float sh = b1[m] - mu1[m] * s;
        const float d12 = ap1[m] - ap2[m];
        const float p2v = ap2[m];
        const float bet = ab[m];
        float4 o;
        float* po = &o.x;
        #pragma unroll
        for (int j = 0; j < 4; ++j) {
            const float v = acc[i][j] * s + sh;
            const float d = d12 * v;
            const float t = bet * d;
            const float sig = 1.0f / (1.0f + __expf(-t));
            po[j] = d * sig + p2v * v;
        }
        *(float4*)&g_y[(size_t)b * MID * PP + (size_t)m * PP + p0 + tp * 4] = o;
    }
}

// ---------------------------------------------------------------------------
// Kernel 2: weight[b,o,p] = BN2( sum_m y[b,m,p] * w2[o,m] ),  o in [0,784)
// Tile: 64 o x 64 px, K=64 single stage. 256 threads, 4x4 regs/thread.
// ---------------------------------------------------------------------------
__global__ __launch_bounds__(256) void k2_conv2_bn(
    const float* __restrict__ w2,
    const float* __restrict__ g2, const float* __restrict__ b2,
    const float* __restrict__ mu2, const float* __restrict__ v2)
{
    __shared__ float w2s[64][68];  // [m][o_local], padded
    __shared__ float ys[64][64];   // [m][px]

    const int tid = threadIdx.x;
    const int b   = blockIdx.z;
    const int o0  = blockIdx.y * 64;
    const int p0  = blockIdx.x * 64;
    const int tm  = tid & 15;
    const int tp  = tid >> 4;

    // stage w2 (transposed) and y tile
    {
        const int m  = tid & 63;
        const int ob = tid >> 6;
        #pragma unroll
        for (int it = 0; it < 16; ++it) {
            const int ol = ob + 4 * it;
            const int o  = o0 + ol;
            w2s[m][ol] = (o < W2O) ? w2[o * MID + m] : 0.0f;
        }
        const int px = tid & 63;
        const int mb = tid >> 6;
        #pragma unroll
        for (int it = 0; it < 16; ++it) {
            const int m2 = mb + 4 * it;
            ys[m2][px] = g_y[(size_t)b * MID * PP + (size_t)m2 * PP + p0 + px];
        }
    }
    __syncthreads();

    float acc[4][4] = {};
    #pragma unroll
    for (int k = 0; k < 64; ++k) {
        const float4 wv = *(const float4*)&w2s[k][tm * 4];
        const float4 yv = *(const float4*)&ys[k][tp * 4];
        acc[0][0] += wv.x * yv.x; acc[0][1] += wv.x * yv.y;
        acc[0][2] += wv.x * yv.z; acc[0][3] += wv.x * yv.w;
        acc[1][0] += wv.y * yv.x; acc[1][1] += wv.y * yv.y;
        acc[1][2] += wv.y * yv.z; acc[1][3] += wv.y * yv.w;
        acc[2][0] += wv.z * yv.x; acc[2][1] += wv.z * yv.y;
        acc[2][2] += wv.z * yv.z; acc[2][3] += wv.z * yv.w;
        acc[3][0] += wv.w * yv.x; acc[3][1] += wv.w * yv.y;
        acc[3][2] += wv.w * yv.z; acc[3][3] += wv.w * yv.w;
    }

    #pragma unroll
    for (int i = 0; i < 4; ++i) {
        const int o = o0 + tm * 4 + i;
        if (o < W2O) {
            const float s  = g2[o] * rsqrtf(v2[o] + BN_EPS);
            const float sh = b2[o] - mu2[o] * s;
            float4 ov;
            ov.x = acc[i][0] * s + sh;
            ov.y = acc[i][1] * s + sh;
            ov.z = acc[i][2] * s + sh;
            ov.w = acc[i][3] * s + sh;
            *(float4*)&g_wt[(size_t)b * W2O * PP + (size_t)o * PP + p0 + tp * 4] = ov;
        }
    }
}

// ---------------------------------------------------------------------------
// Kernel 3: involution.
// out[b, g*16+cl, h, w] = sum_{ky,kx} wt[b, g*49 + ky*7+kx, h, w]
//                                    * x[b, g*16+cl, h+ky-3, w+kx-3]
// Block = (batch, group, 8x8 pixel tile). 256 threads, 4 channels/thread.
// ---------------------------------------------------------------------------
__global__ __launch_bounds__(256) void k3_involution(
    const float* __restrict__ x, float* __restrict__ out)
{
    __shared__ float wts[49][64];       // [kk][pix]  12.5 KB
    __shared__ float xsm[16][14][16];   // [c][r][q]  14.3 KB

    const int tid = threadIdx.x;
    const int b = blockIdx.z;
    const int g = blockIdx.y;
    const int t = blockIdx.x;           // 0..48
    const int h0 = (t / 7) * 8;
    const int w0 = (t % 7) * 8;

    // stage weight tile
    const float* wb = g_wt + (size_t)b * W2O * PP + (size_t)g * 49 * PP;
    for (int idx = tid; idx < 49 * 64; idx += 256) {
        const int kk = idx >> 6;
        const int pix = idx & 63;
        const int iy = pix >> 3, ix = pix & 7;
        wts[kk][pix] = wb[(size_t)kk * PP + (h0 + iy) * HW + (w0 + ix)];
    }
    // stage x halo patch (16 channels, 14x14, zero-padded)
    const float* xg = x + (size_t)b * C1 * PP + (size_t)g * GCH * PP;
    for (int idx = tid; idx < 16 * 196; idx += 256) {
        const int c = idx / 196;
        const int rem = idx - c * 196;
        const int r = rem / 14;
        const int q = rem - r * 14;
        const int h = h0 + r - 3;
        const int w = w0 + q - 3;
        float v = 0.0f;
        if (h >= 0 && h < HW && w >= 0 && w < HW)
            v = xg[(size_t)c * PP + h * HW + w];
        xsm[c][r][q] = v;
    }
    __syncthreads();

    const int px = tid & 63;
    const int iy = px >> 3, ix = px & 7;
    const int cl0 = (tid >> 6) * 4;

    float acc0 = 0.f, acc1 = 0.f, acc2 = 0.f, acc3 = 0.f;
    #pragma unroll
    for (int kk = 0; kk < 49; ++kk) {
        const int dy = kk / 7;
        const int dx = kk - dy * 7;
        const float wv = wts[kk][px];
        acc0 += wv * xsm[cl0 + 0][iy + dy][ix + dx];
        acc1 += wv * xsm[cl0 + 1][iy + dy][ix + dx];
        acc2 += wv * xsm[cl0 + 2][iy + dy][ix + dx];
        acc3 += wv * xsm[cl0 + 3][iy + dy][ix + dx];
    }

    const size_t base = (size_t)b * C1 * PP + (size_t)(g * GCH + cl0) * PP
                        + (h0 + iy) * HW + (w0 + ix);
    out[base + 0 * PP] = acc0;
    out[base + 1 * PP] = acc1;
    out[base + 2 * PP] = acc2;
    out[base + 3 * PP] = acc3;
}

// ---------------------------------------------------------------------------
extern "C" void kernel_launch(void* const* d_in, const int* in_sizes, int n_in,
                              void* d_out, int out_size)
{
    const float* x   = (const float*)d_in[0];
    const float* w1  = (const float*)d_in[1];
    const float* g1  = (const float*)d_in[2];
    const float* b1  = (const float*)d_in[3];
    const float* mu1 = (const float*)d_in[4];
    const float* v1  = (const float*)d_in[5];
    const float* ap1 = (const float*)d_in[6];
    const float* ap2 = (const float*)d_in[7];
    const float* ab  = (const float*)d_in[8];
    const float* w2  = (const float*)d_in[9];
    const float* g2  = (const float*)d_in[10];
    const float* b2  = (const float*)d_in[11];
    const float* mu2 = (const float*)d_in[12];
    const float* v2  = (const float*)d_in[13];
    float* out = (float*)d_out;

    dim3 grid1(PP / 64, BB);            // 49 x 4
    k1_conv1_bn_acon<<<grid1, 256>>>(x, w1, g1, b1, mu1, v1, ap1, ap2, ab);

    dim3 grid2(PP / 64, (W2O + 63) / 64, BB);   // 49 x 13 x 4
    k2_conv2_bn<<<grid2, 256>>>(w2, g2, b2, mu2, v2);

    dim3 grid3(49, NG, BB);             // 49 x 16 x 4
    k3_involution<<<grid3, 256>>>(x, out);
}

// round 2
// speedup vs baseline: 1.0243x; 1.0243x over previous
#include <cuda_runtime.h>

#define BB 4
#define C1 256
#define MID 64
#define HW 56
#define PP 3136       // 56*56
#define NPX 12544     // BB*PP
#define W2O 784       // 49*16
#define BN_EPS 1e-3f

// Scratch intermediates, pixel-major over combined batch*pixels.
__device__ float g_y[MID * NPX];     // 3.2 MB   y[m][b*PP+p]
__device__ float g_wt[W2O * NPX];    // 39.3 MB  wt[o][b*PP+p]

// ---------------------------------------------------------------------------
// Kernel 1: y[m, bp] = ACON(BN1( sum_c x[b,c,p] * w1[m,c] ))
// Tile 32m x 64px, 64 threads, regtile 4m x 8px, K=256 in chunks of 16.
// grid (49, 4, 2)
// ---------------------------------------------------------------------------
__global__ __launch_bounds__(64) void k1_conv1_bn_acon(
    const float* __restrict__ x, const float* __restrict__ w1,
    const float* __restrict__ g1, const float* __restrict__ b1,
    const float* __restrict__ mu1, const float* __restrict__ v1,
    const float* __restrict__ ap1, const float* __restrict__ ap2,
    const float* __restrict__ ab)
{
    __shared__ float xs[16][64];
    __shared__ float ws[16][32];

    const int tid = threadIdx.x;
    const int p0  = blockIdx.x * 64;
    const int b   = blockIdx.y;
    const int m0  = blockIdx.z * 32;
    const int mg  = tid >> 3;     // 0..7  -> 4 m each
    const int pg  = tid & 7;      // 0..7  -> 8 px each

    float acc[4][8] = {};
    const float* xb = x + (size_t)b * C1 * PP + p0;

    for (int k0 = 0; k0 < C1; k0 += 16) {
        // stage w1 chunk transposed: ws[k][m]
        #pragma unroll
        for (int it = 0; it < 2; ++it) {
            const int f  = tid + 64 * it;      // 0..127
            const int m  = f >> 2;             // 0..31
            const int k4 = f & 3;
            const float4 v = *(const float4*)&w1[(m0 + m) * C1 + k0 + k4 * 4];
            ws[k4 * 4 + 0][m] = v.x;
            ws[k4 * 4 + 1][m] = v.y;
            ws[k4 * 4 + 2][m] = v.z;
            ws[k4 * 4 + 3][m] = v.w;
        }
        // stage x chunk: xs[k][px]
        #pragma unroll
        for (int it = 0; it < 4; ++it) {
            const int f  = tid + 64 * it;      // 0..255
            const int k  = f >> 4;             // 0..15
            const int p4 = f & 15;
            *(float4*)&xs[k][p4 * 4] =
                *(const float4*)&xb[(size_t)(k0 + k) * PP + p4 * 4];
        }
        __syncthreads();
        #pragma unroll
        for (int k = 0; k < 16; ++k) {
            const float4 wv = *(const float4*)&ws[k][mg * 4];
            const float4 xa = *(const float4*)&xs[k][pg * 8];
            const float4 xc = *(const float4*)&xs[k][pg * 8 + 4];
            const float wr[4] = {wv.x, wv.y, wv.z, wv.w};
            const float xr[8] = {xa.x, xa.y, xa.z, xa.w, xc.x, xc.y, xc.z, xc.w};
            #pragma unroll
            for (int i = 0; i < 4; ++i)
                #pragma unroll
                for (int j = 0; j < 8; ++j)
                    acc[i][j] += wr[i] * xr[j];
        }
        __syncthreads();
    }

    // Epilogue: BN1 + ACON-C
    #pragma unroll
    for (int i = 0; i < 4; ++i) {
        const int m = m0 + mg * 4 + i;
        const float s   = g1[m] * rsqrtf(v1[m] + BN_EPS);
        const float sh  = b1[m] - mu1[m] * s;
        const float d12 = ap1[m] - ap2[m];
        const float p2v = ap2[m];
        const float bet = ab[m];
        float o[8];
        #pragma unroll
        for (int j = 0; j < 8; ++j) {
            const float v = acc[i][j] * s + sh;
            const float d = d12 * v;
            const float sig = 1.0f / (1.0f + __expf(-bet * d));
            o[j] = d * sig + p2v * v;
        }
        float* dst = &g_y[(size_t)m * NPX + (size_t)b * PP + p0 + pg * 8];
        *(float4*)&dst[0] = make_float4(o[0], o[1], o[2], o[3]);
        *(float4*)&dst[4] = make_float4(o[4], o[5], o[6], o[7]);
    }
}

// ---------------------------------------------------------------------------
// Kernel 2: wt[o, bp] = BN2( sum_m y[m, bp] * w2[o,m] )
// Tile 64o x 128px, 256 threads, regtile 4o x 8px, full K=64 staged.
// grid (98, 13)
// ---------------------------------------------------------------------------
__global__ __launch_bounds__(256) void k2_conv2_bn(
    const float* __restrict__ w2,
    const float* __restrict__ g2, const float* __restrict__ b2,
    const float* __restrict__ mu2, const float* __restrict__ v2)
{
    __shared__ float w2s[64][64];   // [k][o_local] 16KB
    __shared__ float ys[64][128];   // [k][px]      32KB

    const int tid = threadIdx.x;
    const int bp0 = blockIdx.x * 128;
    const int o0  = blockIdx.y * 64;
    const int og  = tid >> 4;       // 0..15 -> 4 o each
    const int pg  = tid & 15;       // 0..15 -> 8 px each

    // stage w2 transposed (guarded, zero-fill)
    #pragma unroll
    for (int it = 0; it < 4; ++it) {
        const int f  = tid + 256 * it;   // 0..1023
        const int ol = f >> 4;           // 0..63
        const int k4 = f & 15;
        float4 v = make_float4(0.f, 0.f, 0.f, 0.f);
        if (o0 + ol < W2O)
            v = *(const float4*)&w2[(o0 + ol) * MID + k4 * 4];
        w2s[k4 * 4 + 0][ol] = v.x;
        w2s[k4 * 4 + 1][ol] = v.y;
        w2s[k4 * 4 + 2][ol] = v.z;
        w2s[k4 * 4 + 3][ol] = v.w;
    }
    // stage y tile
    #pragma unroll
    for (int it = 0; it < 8; ++it) {
        const int f  = tid + 256 * it;   // 0..2047
        const int k  = f >> 5;           // 0..63
        const int p4 = f & 31;
        *(float4*)&ys[k][p4 * 4] =
            *(const float4*)&g_y[(size_t)k * NPX + bp0 + p4 * 4];
    }
    __syncthreads();

    float acc[4][8] = {};
    #pragma unroll 8
    for (int k = 0; k < 64; ++k) {
        const float4 wv = *(const float4*)&w2s[k][og * 4];
        const float4 ya = *(const float4*)&ys[k][pg * 8];
        const float4 yb = *(const float4*)&ys[k][pg * 8 + 4];
        const float wr[4] = {wv.x, wv.y, wv.z, wv.w};
        const float yr[8] = {ya.x, ya.y, ya.z, ya.w, yb.x, yb.y, yb.z, yb.w};
        #pragma unroll
        for (int i = 0; i < 4; ++i)
            #pragma unroll
            for (int j = 0; j < 8; ++j)
                acc[i][j] += wr[i] * yr[j];
    }

    #pragma unroll
    for (int i = 0; i < 4; ++i) {
        const int o = o0 + og * 4 + i;
        if (o < W2O) {
            const float s  = g2[o] * rsqrtf(v2[o] + BN_EPS);
            const float sh = b2[o] - mu2[o] * s;
            float* dst = &g_wt[(size_t)o * NPX + bp0 + pg * 8];
            *(float4*)&dst[0] = make_float4(acc[i][0] * s + sh, acc[i][1] * s + sh,
                                            acc[i][2] * s + sh, acc[i][3] * s + sh);
            *(float4*)&dst[4] = make_float4(acc[i][4] * s + sh, acc[i][5] * s + sh,
                                            acc[i][6] * s + sh, acc[i][7] * s + sh);
        }
    }
}

// ---------------------------------------------------------------------------
// Kernel 3: involution.
// out[b, g*16+c, h, w] = sum_kk wt[g*49+kk, bp(h,w)] * x[b, g*16+c, h+dy-3, w+dx-3]
// Block = 32 threads, tile = 8x8 px, 1 group, 1 batch.
// Thread owns 4 channels x one 8-px row; x-window in registers,
// weights streamed directly from global (each element read exactly once).
// grid (49, 16, 4)
// ---------------------------------------------------------------------------
__global__ __launch_bounds__(32) void k3_involution(
    const float* __restrict__ x, float* __restrict__ out)
{
    __shared__ float xsm[16][14][20];   // pad row stride 20 -> conflict-free

    const int tid = threadIdx.x;
    const int t = blockIdx.x;           // 0..48
    const int g = blockIdx.y;
    const int b = blockIdx.z;
    const int h0 = (t / 7) * 8;
    const int w0 = (t % 7) * 8;

    const int row = tid & 7;            // output row within tile
    const int cg  = tid >> 3;           // 0..3
    const int c0  = cg * 4;

    // stage x halo (16 ch, 14x14, zero padded)
    const float* xg = x + (size_t)b * C1 * PP + (size_t)g * 16 * PP;
    for (int idx = tid; idx < 16 * 196; idx += 32) {
        const int c = idx / 196;
        const int rem = idx - c * 196;
        const int r = rem / 14;
        const int q = rem - r * 14;
        const int h = h0 + r - 3;
        const int w = w0 + q - 3;
        float v = 0.0f;
        if (h >= 0 && h < HW && w >= 0 && w < HW)
            v = xg[(size_t)c * PP + h * HW + w];
        xsm[c][r][q] = v;
    }
    __syncthreads();

    float acc[4][8] = {};
    const float* wbase = g_wt + (size_t)(g * 49) * NPX
                              + (size_t)b * PP + (h0 + row) * HW + w0;

    #pragma unroll 1
    for (int dy = 0; dy < 7; ++dy) {
        // x window registers: 4 channels x 16 floats (14 used)
        float xr[4][16];
        #pragma unroll
        for (int c = 0; c < 4; ++c)
            #pragma unroll
            for (int q4 = 0; q4 < 4; ++q4)
                *(float4*)&xr[c][q4 * 4] =
                    *(const float4*)&xsm[c0 + c][row + dy][q4 * 4];

        #pragma unroll
        for (int dx = 0; dx < 7; ++dx) {
            const float* wp = wbase + (size_t)(dy * 7 + dx) * NPX;
            const float4 wa = *(const float4*)&wp[0];
            const float4 wb = *(const float4*)&wp[4];
            const float wj[8] = {wa.x, wa.y, wa.z, wa.w, wb.x, wb.y, wb.z, wb.w};
            #pragma unroll
            for (int c = 0; c < 4; ++c)
                #pragma unroll
                for (int j = 0; j < 8; ++j)
                    acc[c][j] += wj[j] * xr[c][dx + j];
        }
    }

    #pragma unroll
    for (int c = 0; c < 4; ++c) {
        float* dst = out + ((size_t)b * C1 + g * 16 + c0 + c) * PP
                         + (h0 + row) * HW + w0;
        *(float4*)&dst[0] = make_float4(acc[c][0], acc[c][1], acc[c][2], acc[c][3]);
        *(float4*)&dst[4] = make_float4(acc[c][4], acc[c][5], acc[c][6], acc[c][7]);
    }
}

// ---------------------------------------------------------------------------
extern "C" void kernel_launch(void* const* d_in, const int* in_sizes, int n_in,
                              void* d_out, int out_size)
{
    const float* x   = (const float*)d_in[0];
    const float* w1  = (const float*)d_in[1];
    const float* g1  = (const float*)d_in[2];
    const float* b1  = (const float*)d_in[3];
    const float* mu1 = (const float*)d_in[4];
    const float* v1  = (const float*)d_in[5];
    const float* ap1 = (const float*)d_in[6];
    const float* ap2 = (const float*)d_in[7];
    const float* ab  = (const float*)d_in[8];
    const float* w2  = (const float*)d_in[9];
    const float* g2  = (const float*)d_in[10];
    const float* b2  = (const float*)d_in[11];
    const float* mu2 = (const float*)d_in[12];
    const float* v2  = (const float*)d_in[13];
    float* out = (float*)d_out;

    dim3 grid1(PP / 64, BB, 2);              // 49 x 4 x 2 = 392 blocks
    k1_conv1_bn_acon<<<grid1, 64>>>(x, w1, g1, b1, mu1, v1, ap1, ap2, ab);

    dim3 grid2(NPX / 128, (W2O + 63) / 64);  // 98 x 13 = 1274 blocks
    k2_conv2_bn<<<grid2, 256>>>(w2, g2, b2, mu2, v2);

    dim3 grid3(49, 16, BB);                  // 3136 blocks of 32 threads
    k3_involution<<<grid3, 32>>>(x, out);
}

// round 3
// speedup vs baseline: 1.5452x; 1.5085x over previous
#include <cuda_runtime.h>
#include <cstdint>

#define BB 4
#define C1 256
#define MID 64
#define HW 56
#define PP 3136       // 56*56
#define NPX 12544     // BB*PP
#define W2O 784       // 49*16
#define BN_EPS 1e-3f

// Scratch intermediates.
__device__ float g_y[NPX * MID];     // pixel-major: y[bp][m]   3.2 MB
__device__ float g_wt[W2O * NPX];    // o-major:     wt[o][bp]  39.3 MB

// ---------------------------------------------------------------------------
__device__ __forceinline__ uint32_t f2tf(float f) {
    uint32_t u;
    asm("cvt.rna.tf32.f32 %0, %1;" : "=r"(u) : "f"(f));
    return u;
}
__device__ __forceinline__ float4 cvt4(float4 v) {
    v.x = __uint_as_float(f2tf(v.x));
    v.y = __uint_as_float(f2tf(v.y));
    v.z = __uint_as_float(f2tf(v.z));
    v.w = __uint_as_float(f2tf(v.w));
    return v;
}
__device__ __forceinline__ void mma_tf32(float* c, uint32_t a0, uint32_t a1,
                                         uint32_t a2, uint32_t a3,
                                         uint32_t b0, uint32_t b1) {
    asm volatile(
        "mma.sync.aligned.m16n8k8.row.col.f32.tf32.tf32.f32 "
        "{%0,%1,%2,%3}, {%4,%5,%6,%7}, {%8,%9}, {%0,%1,%2,%3};\n"
        : "+f"(c[0]), "+f"(c[1]), "+f"(c[2]), "+f"(c[3])
        : "r"(a0), "r"(a1), "r"(a2), "r"(a3), "r"(b0), "r"(b1));
}
__device__ __forceinline__ float aconf(float v, float d12, float p2, float bet) {
    const float d = d12 * v;
    const float sig = 1.0f / (1.0f + __expf(-bet * d));
    return d * sig + p2 * v;
}

// ---------------------------------------------------------------------------
// Kernel 1 (tf32 MMA): y[bp][m] = ACON(BN1( sum_c x[b,c,p] * w1[m,c] ))
// Block: 128 thr (4 warps), tile 64px x 64m, K=256 in chunks of 32.
// grid = 196.
// ---------------------------------------------------------------------------
__global__ __launch_bounds__(128) void k1_conv1_bn_acon(
    const float* __restrict__ x, const float* __restrict__ w1,
    const float* __restrict__ g1, const float* __restrict__ b1,
    const float* __restrict__ mu1, const float* __restrict__ v1,
    const float* __restrict__ ap1, const float* __restrict__ ap2,
    const float* __restrict__ ab)
{
    __shared__ float xs[32][72];   // [k][px]  pad 72: A-frag conflict-free
    __shared__ float ws[64][36];   // [m][k]   pad 36: B-frag conflict-free

    const int tid  = threadIdx.x;
    const int wrp  = tid >> 5;
    const int lane = tid & 31;
    const int g    = lane >> 2;
    const int tig  = lane & 3;

    const int bp0 = blockIdx.x * 64;
    const int b   = blockIdx.x / 49;
    const int p0  = (blockIdx.x % 49) * 64;

    float acc[8][4] = {};
    const float* xb = x + (size_t)b * C1 * PP + p0;

    for (int kc = 0; kc < 8; ++kc) {
        const int k0 = kc * 32;
        // stage x chunk: xs[k][px], coalesced, tf32-rounded
        #pragma unroll
        for (int it = 0; it < 4; ++it) {
            const int f = tid + 128 * it;       // 0..511
            const int r = f >> 4, q4 = f & 15;
            float4 v = *(const float4*)&xb[(size_t)(k0 + r) * PP + q4 * 4];
            *(float4*)&xs[r][q4 * 4] = cvt4(v);
        }
        // stage w1 chunk: ws[m][k]
        #pragma unroll
        for (int it = 0; it < 4; ++it) {
            const int f = tid + 128 * it;       // 0..511
            const int r = f >> 3, q4 = f & 7;
            float4 v = *(const float4*)&w1[r * C1 + k0 + q4 * 4];
            *(float4*)&ws[r][q4 * 4] = cvt4(v);
        }
        __syncthreads();

        #pragma unroll
        for (int ks = 0; ks < 4; ++ks) {
            const int kb = ks * 8;
            const int pxr = wrp * 16 + g;
            const uint32_t a0 = __float_as_uint(xs[kb + tig    ][pxr]);
            const uint32_t a1 = __float_as_uint(xs[kb + tig    ][pxr + 8]);
            const uint32_t a2 = __float_as_uint(xs[kb + tig + 4][pxr]);
            const uint32_t a3 = __float_as_uint(xs[kb + tig + 4][pxr + 8]);
            #pragma unroll
            for (int n = 0; n < 8; ++n) {
                const uint32_t b0 = __float_as_uint(ws[n * 8 + g][kb + tig]);
                const uint32_t b1 = __float_as_uint(ws[n * 8 + g][kb + tig + 4]);
                mma_tf32(acc[n], a0, a1, a2, a3, b0, b1);
            }
        }
        __syncthreads();
    }

    // Epilogue: BN1 + ACON, write pixel-major y[bp][m]
    const int pxr = wrp * 16 + g;
    #pragma unroll
    for (int n = 0; n < 8; ++n) {
        const int ma = n * 8 + 2 * tig;
        const int mb = ma + 1;
        const float sA  = g1[ma] * rsqrtf(v1[ma] + BN_EPS);
        const float shA = b1[ma] - mu1[ma] * sA;
        const float sB  = g1[mb] * rsqrtf(v1[mb] + BN_EPS);
        const float shB = b1[mb] - mu1[mb] * sB;
        const float dA = ap1[ma] - ap2[ma], pA = ap2[ma], bA = ab[ma];
        const float dB = ap1[mb] - ap2[mb], pB = ap2[mb], bB = ab[mb];

        float2 o01, o23;
        o01.x = aconf(acc[n][0] * sA + shA, dA, pA, bA);
        o01.y = aconf(acc[n][1] * sB + shB, dB, pB, bB);
        o23.x = aconf(acc[n][2] * sA + shA, dA, pA, bA);
        o23.y = aconf(acc[n][3] * sB + shB, dB, pB, bB);

        *(float2*)&g_y[(size_t)(bp0 + pxr    ) * MID + ma] = o01;
        *(float2*)&g_y[(size_t)(bp0 + pxr + 8) * MID + ma] = o23;
    }
}

// ---------------------------------------------------------------------------
// Kernel 2 (tf32 MMA): wt[o][bp] = BN2( sum_m y[bp][m] * w2[o][m] )
// Block: 224 thr (7 warps), tile 112px x 64o, K=64 staged once.
// Epilogue transposes through smem so output is o-major (k3 contract).
// grid = (112, 13).
// ---------------------------------------------------------------------------
__global__ __launch_bounds__(224) void k2_conv2_bn(
    const float* __restrict__ w2,
    const float* __restrict__ g2, const float* __restrict__ b2,
    const float* __restrict__ mu2, const float* __restrict__ v2)
{
    __shared__ float pool[112 * 68 + 64 * 68];   // 47872 B
    float* ys = pool;                // [px][68]  A: stride 68 -> lane-distinct banks
    float* ws = pool + 112 * 68;     // [o][68]   B: stride 68
    float* tr = pool;                // aliased transpose buf [o][116]

    const int tid  = threadIdx.x;
    const int wrp  = tid >> 5;       // 0..6
    const int lane = tid & 31;
    const int g    = lane >> 2;
    const int tig  = lane & 3;

    const int bp0 = blockIdx.x * 112;
    const int o0  = blockIdx.y * 64;

    // stage y tile (tf32)
    #pragma unroll
    for (int it = 0; it < 8; ++it) {
        const int f = tid + 224 * it;          // 0..1791
        const int px = f >> 4, q4 = f & 15;
        float4 v = *(const float4*)&g_y[(size_t)(bp0 + px) * MID + q4 * 4];
        *(float4*)&ys[px * 68 + q4 * 4] = cvt4(v);
    }
    // stage w2 tile (tf32, zero-fill tail)
    for (int f = tid; f < 1024; f += 224) {
        const int o = f >> 4, q4 = f & 15;
        float4 v = make_float4(0.f, 0.f, 0.f, 0.f);
        if (o0 + o < W2O)
            v = *(const float4*)&w2[(o0 + o) * MID + q4 * 4];
        *(float4*)&ws[o * 68 + q4 * 4] = cvt4(v);
    }
    __syncthreads();

    float acc[8][4] = {};
    const int pxr = wrp * 16 + g;
    #pragma unroll
    for (int ks = 0; ks < 8; ++ks) {
        const int kb = ks * 8;
        const uint32_t a0 = __float_as_uint(ys[(pxr    ) * 68 + kb + tig]);
        const uint32_t a1 = __float_as_uint(ys[(pxr + 8) * 68 + kb + tig]);
        const uint32_t a2 = __float_as_uint(ys[(pxr    ) * 68 + kb + tig + 4]);
        const uint32_t a3 = __float_as_uint(ys[(pxr + 8) * 68 + kb + tig + 4]);
        #pragma unroll
        for (int n = 0; n < 8; ++n) {
            const uint32_t b0 = __float_as_uint(ws[(n * 8 + g) * 68 + kb + tig]);
            const uint32_t b1 = __float_as_uint(ws[(n * 8 + g) * 68 + kb + tig + 4]);
            mma_tf32(acc[n], a0, a1, a2, a3, b0, b1);
        }
    }
    __syncthreads();   // done reading ys/ws; tr aliases them

    // BN + transpose into smem [o_local][px]
    #pragma unroll
    for (int n = 0; n < 8; ++n) {
        const int ola = n * 8 + 2 * tig;
        const int oa = o0 + ola, ob = oa + 1;
        float sA = 0.f, shA = 0.f, sB = 0.f, shB = 0.f;
        if (oa < W2O) { sA = g2[oa] * rsqrtf(v2[oa] + BN_EPS); shA = b2[oa] - mu2[oa] * sA; }
        if (ob < W2O) { sB = g2[ob] * rsqrtf(v2[ob] + BN_EPS); shB = b2[ob] - mu2[ob] * sB; }
        tr[(ola    ) * 116 + pxr    ] = acc[n][0] * sA + shA;
        tr[(ola + 1) * 116 + pxr    ] = acc[n][1] * sB + shB;
        tr[(ola    ) * 116 + pxr + 8] = acc[n][2] * sA + shA;
        tr[(ola + 1) * 116 + pxr + 8] = acc[n][3] * sB + shB;
    }
    __syncthreads();

    // coalesced o-major store: 64 rows x 28 float4
    #pragma unroll
    for (int it = 0; it < 8; ++it) {
        const int f = tid + 224 * it;          // 0..1791
        const int ol = f / 28, p4 = f % 28;
        if (o0 + ol < W2O)
            *(float4*)&g_wt[(size_t)(o0 + ol) * NPX + bp0 + p4 * 4] =
                *(const float4*)&tr[ol * 116 + p4 * 4];
    }
}

// ---------------------------------------------------------------------------
// Kernel 3: involution (unchanged contract: g_wt o-major).
// Block = 32 threads, tile = 8x8 px, 1 group, 1 batch.
// grid (49, 16, 4)
// ---------------------------------------------------------------------------
__global__ __launch_bounds__(32) void k3_involution(
    const float* __restrict__ x, float* __restrict__ out)
{
    __shared__ float xsm[16][14][20];

    const int tid = threadIdx.x;
    const int t = blockIdx.x;
    const int g = blockIdx.y;
    const int b = blockIdx.z;
    const int h0 = (t / 7) * 8;
    const int w0 = (t % 7) * 8;

    const int row = tid & 7;
    const int cg  = tid >> 3;
    const int c0  = cg * 4;

    const float* xg = x + (size_t)b * C1 * PP + (size_t)g * 16 * PP;
    for (int idx = tid; idx < 16 * 196; idx += 32) {
        const int c = idx / 196;
        const int rem = idx - c * 196;
        const int r = rem / 14;
        const int q = rem - r * 14;
        const int h = h0 + r - 3;
        const int w = w0 + q - 3;
        float v = 0.0f;
        if (h >= 0 && h < HW && w >= 0 && w < HW)
            v = xg[(size_t)c * PP + h * HW + w];
        xsm[c][r][q] = v;
    }
    __syncthreads();

    float acc[4][8] = {};
    const float* wbase = g_wt + (size_t)(g * 49) * NPX
                              + (size_t)b * PP + (h0 + row) * HW + w0;

    #pragma unroll 1
    for (int dy = 0; dy < 7; ++dy) {
        float xr[4][16];
        #pragma unroll
        for (int c = 0; c < 4; ++c)
            #pragma unroll
            for (int q4 = 0; q4 < 4; ++q4)
                *(float4*)&xr[c][q4 * 4] =
                    *(const float4*)&xsm[c0 + c][row + dy][q4 * 4];

        #pragma unroll
        for (int dx = 0; dx < 7; ++dx) {
            const float* wp = wbase + (size_t)(dy * 7 + dx) * NPX;
            const float4 wa = *(const float4*)&wp[0];
            const float4 wb = *(const float4*)&wp[4];
            const float wj[8] = {wa.x, wa.y, wa.z, wa.w, wb.x, wb.y, wb.z, wb.w};
            #pragma unroll
            for (int c = 0; c < 4; ++c)
                #pragma unroll
                for (int j = 0; j < 8; ++j)
                    acc[c][j] += wj[j] * xr[c][dx + j];
        }
    }

    #pragma unroll
    for (int c = 0; c < 4; ++c) {
        float* dst = out + ((size_t)b * C1 + g * 16 + c0 + c) * PP
                         + (h0 + row) * HW + w0;
        *(float4*)&dst[0] = make_float4(acc[c][0], acc[c][1], acc[c][2], acc[c][3]);
        *(float4*)&dst[4] = make_float4(acc[c][4], acc[c][5], acc[c][6], acc[c][7]);
    }
}

// ---------------------------------------------------------------------------
extern "C" void kernel_launch(void* const* d_in, const int* in_sizes, int n_in,
                              void* d_out, int out_size)
{
    const float* x   = (const float*)d_in[0];
    const float* w1  = (const float*)d_in[1];
    const float* g1  = (const float*)d_in[2];
    const float* b1  = (const float*)d_in[3];
    const float* mu1 = (const float*)d_in[4];
    const float* v1  = (const float*)d_in[5];
    const float* ap1 = (const float*)d_in[6];
    const float* ap2 = (const float*)d_in[7];
    const float* ab  = (const float*)d_in[8];
    const float* w2  = (const float*)d_in[9];
    const float* g2  = (const float*)d_in[10];
    const float* b2  = (const float*)d_in[11];
    const float* mu2 = (const float*)d_in[12];
    const float* v2  = (const float*)d_in[13];
    float* out = (float*)d_out;

    k1_conv1_bn_acon<<<NPX / 64, 128>>>(x, w1, g1, b1, mu1, v1, ap1, ap2, ab);

    dim3 grid2(NPX / 112, 13);
    k2_conv2_bn<<<grid2, 224>>>(w2, g2, b2, mu2, v2);

    dim3 grid3(49, 16, BB);
    k3_involution<<<grid3, 32>>>(x, out);
}

// round 4
// speedup vs baseline: 1.6917x; 1.0948x over previous
#include <cuda_runtime.h>
#include <cstdint>

#define BB 4
#define C1 256
#define MID 64
#define HW 56
#define PP 3136       // 56*56
#define NPX 12544     // BB*PP
#define W2O 784       // 49*16
#define BN_EPS 1e-3f

// Intermediate: y pixel-major y[bp][m]
__device__ float g_y[NPX * MID];     // 3.2 MB (L2-resident)

// ---------------------------------------------------------------------------
__device__ __forceinline__ uint32_t f2tf(float f) {
    uint32_t u;
    asm("cvt.rna.tf32.f32 %0, %1;" : "=r"(u) : "f"(f));
    return u;
}
__device__ __forceinline__ float4 cvt4(float4 v) {
    v.x = __uint_as_float(f2tf(v.x));
    v.y = __uint_as_float(f2tf(v.y));
    v.z = __uint_as_float(f2tf(v.z));
    v.w = __uint_as_float(f2tf(v.w));
    return v;
}
__device__ __forceinline__ void mma_tf32(float* c, uint32_t a0, uint32_t a1,
                                         uint32_t a2, uint32_t a3,
                                         uint32_t b0, uint32_t b1) {
    asm volatile(
        "mma.sync.aligned.m16n8k8.row.col.f32.tf32.tf32.f32 "
        "{%0,%1,%2,%3}, {%4,%5,%6,%7}, {%8,%9}, {%0,%1,%2,%3};\n"
        : "+f"(c[0]), "+f"(c[1]), "+f"(c[2]), "+f"(c[3])
        : "r"(a0), "r"(a1), "r"(a2), "r"(a3), "r"(b0), "r"(b1));
}
__device__ __forceinline__ float aconf(float v, float d12, float p2, float bet) {
    const float d = d12 * v;
    const float sig = 1.0f / (1.0f + __expf(-bet * d));
    return d * sig + p2 * v;
}

// ---------------------------------------------------------------------------
// Kernel 1 (tf32 MMA, double-buffered): y[bp][m] = ACON(BN1(x @ w1^T))
// Block 128 thr, tile 32px x 64m, K=256 in chunks of 32, grid 392.
// Warp w: px-half (w&1)*16, n-half (w>>1)*32.
// ---------------------------------------------------------------------------
__global__ __launch_bounds__(128) void k1_conv1_bn_acon(
    const float* __restrict__ x, const float* __restrict__ w1,
    const float* __restrict__ g1, const float* __restrict__ b1,
    const float* __restrict__ mu1, const float* __restrict__ v1,
    const float* __restrict__ ap1, const float* __restrict__ ap2,
    const float* __restrict__ ab)
{
    __shared__ float xs[2][32][40];   // [k][px] pad 40 (≡8 mod 32)
    __shared__ float ws[2][64][36];   // [m][k]  pad 36 (≡4 mod 32)

    const int tid  = threadIdx.x;
    const int wrp  = tid >> 5;
    const int lane = tid & 31;
    const int g    = lane >> 2;
    const int tig  = lane & 3;
    const int pxg  = wrp & 1;
    const int nh   = wrp >> 1;

    const int b  = blockIdx.x / 98;
    const int p0 = (blockIdx.x % 98) * 32;
    const float* xb = x + (size_t)b * C1 * PP + p0;

    const int xk = tid >> 3;          // staging coords (x): k row 0..15? no:
    // x staging: 256 f4 over 2 iters: f = tid + 128*it -> k=f>>3 (0..31), q=f&7
    // w staging: 512 f4 over 4 iters: f = tid + 128*it -> m=f>>3 (0..63), q=f&7
    float4 xv[2], wv[4];

    // ---- prologue: ldg + sts chunk 0
    #pragma unroll
    for (int it = 0; it < 2; ++it) {
        const int f = tid + 128 * it, k = f >> 3, q = f & 7;
        xv[it] = *(const float4*)&xb[(size_t)k * PP + q * 4];
    }
    #pragma unroll
    for (int it = 0; it < 4; ++it) {
        const int f = tid + 128 * it, m = f >> 3, q = f & 7;
        wv[it] = *(const float4*)&w1[m * C1 + q * 4];
    }
    #pragma unroll
    for (int it = 0; it < 2; ++it) {
        const int f = tid + 128 * it, k = f >> 3, q = f & 7;
        *(float4*)&xs[0][k][q * 4] = cvt4(xv[it]);
    }
    #pragma unroll
    for (int it = 0; it < 4; ++it) {
        const int f = tid + 128 * it, m = f >> 3, q = f & 7;
        *(float4*)&ws[0][m][q * 4] = cvt4(wv[it]);
    }
    __syncthreads();

    float acc[4][4] = {};
    const int pxr = pxg * 16 + g;

    for (int kc = 0; kc < 8; ++kc) {
        if (kc < 7) {
            const int k0n = (kc + 1) * 32;
            #pragma unroll
            for (int it = 0; it < 2; ++it) {
                const int f = tid + 128 * it, k = f >> 3, q = f & 7;
                xv[it] = *(const float4*)&xb[(size_t)(k0n + k) * PP + q * 4];
            }
            #pragma unroll
            for (int it = 0; it < 4; ++it) {
                const int f = tid + 128 * it, m = f >> 3, q = f & 7;
                wv[it] = *(const float4*)&w1[m * C1 + k0n + q * 4];
            }
        }
        const int buf = kc & 1;
        #pragma unroll
        for (int ks = 0; ks < 4; ++ks) {
            const int kb = ks * 8;
            const uint32_t a0 = __float_as_uint(xs[buf][kb + tig    ][pxr]);
            const uint32_t a1 = __float_as_uint(xs[buf][kb + tig    ][pxr + 8]);
            const uint32_t a2 = __float_as_uint(xs[buf][kb + tig + 4][pxr]);
            const uint32_t a3 = __float_as_uint(xs[buf][kb + tig + 4][pxr + 8]);
            #pragma unroll
            for (int j = 0; j < 4; ++j) {
                const int m = nh * 32 + j * 8 + g;
                const uint32_t b0 = __float_as_uint(ws[buf][m][kb + tig]);
                const uint32_t b1 = __float_as_uint(ws[buf][m][kb + tig + 4]);
                mma_tf32(acc[j], a0, a1, a2, a3, b0, b1);
            }
        }
        __syncthreads();
        if (kc < 7) {
            const int nb = (kc + 1) & 1;
            #pragma unroll
            for (int it = 0; it < 2; ++it) {
                const int f = tid + 128 * it, k = f >> 3, q = f & 7;
                *(float4*)&xs[nb][k][q * 4] = cvt4(xv[it]);
            }
            #pragma unroll
            for (int it = 0; it < 4; ++it) {
                const int f = tid + 128 * it, m = f >> 3, q = f & 7;
                *(float4*)&ws[nb][m][q * 4] = cvt4(wv[it]);
            }
            __syncthreads();
        }
    }

    // Epilogue: BN1 + ACON, write pixel-major y[bp][m]
    const size_t bp0 = (size_t)b * PP + p0;
    #pragma unroll
    for (int j = 0; j < 4; ++j) {
        const int ma = nh * 32 + j * 8 + 2 * tig;
        const int mb = ma + 1;
        const float sA  = g1[ma] * rsqrtf(v1[ma] + BN_EPS);
        const float shA = b1[ma] - mu1[ma] * sA;
        const float sB  = g1[mb] * rsqrtf(v1[mb] + BN_EPS);
        const float shB = b1[mb] - mu1[mb] * sB;
        const float dA = ap1[ma] - ap2[ma], pA = ap2[ma], bA = ab[ma];
        const float dB = ap1[mb] - ap2[mb], pB = ap2[mb], bB = ab[mb];

        float2 o01, o23;
        o01.x = aconf(acc[j][0] * sA + shA, dA, pA, bA);
        o01.y = aconf(acc[j][1] * sB + shB, dB, pB, bB);
        o23.x = aconf(acc[j][2] * sA + shA, dA, pA, bA);
        o23.y = aconf(acc[j][3] * sB + shB, dB, pB, bB);

        *(float2*)&g_y[(bp0 + pxr    ) * MID + ma] = o01;
        *(float2*)&g_y[(bp0 + pxr + 8) * MID + ma] = o23;
    }
}

// ---------------------------------------------------------------------------
// Kernel 23 (fused): per (tile, group, batch) block:
//   1. GEMM (tf32): wloc[49 o][64 px] = BN2( y_tile[64px][64k] @ w2_g[49][64k]^T )
//   2. involution: out[c][px] = sum_kk wloc[kk][px] * x[c][px shifted]
// Block 128 thr, grid (49, 16, 4). Smem pool aliased across phases.
// ---------------------------------------------------------------------------
__global__ __launch_bounds__(128) void k23_fused(
    const float* __restrict__ x, const float* __restrict__ w2,
    const float* __restrict__ g2, const float* __restrict__ b2,
    const float* __restrict__ mu2, const float* __restrict__ v2,
    float* __restrict__ out)
{
    __shared__ float pool[8160];     // 32640 B
    float* ys  = pool;               // phase A: [64 px][68]
    float* w2s = pool + 64 * 68;     // phase A: [56 o ][68]
    float* wsm = pool;               // phase B: [49 o ][68]  (px-major rows)
    float* xsm = pool + 49 * 68;     // phase B: [16 c][14][20]

    const int tid  = threadIdx.x;
    const int wrp  = tid >> 5;
    const int lane = tid & 31;
    const int g    = lane >> 2;
    const int tig  = lane & 3;

    const int t  = blockIdx.x;       // 0..48
    const int gr = blockIdx.y;       // group
    const int b  = blockIdx.z;
    const int h0 = (t / 7) * 8;
    const int w0 = (t % 7) * 8;

    // ---- Phase A: stage y tile + w2 slice (tf32)
    #pragma unroll
    for (int it = 0; it < 8; ++it) {
        const int f = tid + 128 * it;            // 0..1023
        const int row = f >> 7;                  // 0..7 spatial row
        const int q   = f & 127;                 // float4 within 8px*64m row
        const size_t bp = (size_t)b * PP + (h0 + row) * HW + w0;
        float4 v = *(const float4*)&g_y[bp * MID + q * 4];
        const int pxl = row * 8 + (q >> 4);      // local px 0..63
        *(float4*)&ys[pxl * 68 + (q & 15) * 4] = cvt4(v);
    }
    #pragma unroll
    for (int it = 0; it < 7; ++it) {
        const int f = tid + 128 * it;            // 0..895
        const int o = f >> 4, q4 = f & 15;       // o 0..55
        float4 v = make_float4(0.f, 0.f, 0.f, 0.f);
        if (o < 49)
            v = *(const float4*)&w2[(gr * 49 + o) * MID + q4 * 4];
        *(float4*)&w2s[o * 68 + q4 * 4] = cvt4(v);
    }
    __syncthreads();

    // ---- GEMM: warp wrp handles px rows wrp*16..+15, all 56 o
    float acc[7][4] = {};
    const int pxr = wrp * 16 + g;
    #pragma unroll
    for (int ks = 0; ks < 8; ++ks) {
        const int kb = ks * 8;
        const uint32_t a0 = __float_as_uint(ys[(pxr    ) * 68 + kb + tig]);
        const uint32_t a1 = __float_as_uint(ys[(pxr + 8) * 68 + kb + tig]);
        const uint32_t a2 = __float_as_uint(ys[(pxr    ) * 68 + kb + tig + 4]);
        const uint32_t a3 = __float_as_uint(ys[(pxr + 8) * 68 + kb + tig + 4]);
        #pragma unroll
        for (int n = 0; n < 7; ++n) {
            const uint32_t b0 = __float_as_uint(w2s[(n * 8 + g) * 68 + kb + tig]);
            const uint32_t b1 = __float_as_uint(w2s[(n * 8 + g) * 68 + kb + tig + 4]);
            mma_tf32(acc[n], a0, a1, a2, a3, b0, b1);
        }
    }
    __syncthreads();   // done reading ys/w2s; pool is repurposed

    // ---- Phase B: BN2 + scatter into wsm[o][px]
    #pragma unroll
    for (int n = 0; n < 7; ++n) {
        const int ola = n * 8 + 2 * tig;
        const int olb = ola + 1;
        if (ola < 49) {
            const int o = gr * 49 + ola;
            const float s  = g2[o] * rsqrtf(v2[o] + BN_EPS);
            const float sh = b2[o] - mu2[o] * s;
            wsm[ola * 68 + pxr    ] = acc[n][0] * s + sh;
            wsm[ola * 68 + pxr + 8] = acc[n][2] * s + sh;
        }
        if (olb < 49) {
            const int o = gr * 49 + olb;
            const float s  = g2[o] * rsqrtf(v2[o] + BN_EPS);
            const float sh = b2[o] - mu2[o] * s;
            wsm[olb * 68 + pxr    ] = acc[n][1] * s + sh;
            wsm[olb * 68 + pxr + 8] = acc[n][3] * s + sh;
        }
    }

    // stage x halo (16 ch, 14x14, zero padded) into xsm
    const float* xg = x + (size_t)b * C1 * PP + (size_t)gr * 16 * PP;
    for (int idx = tid; idx < 16 * 196; idx += 128) {
        const int c = idx / 196;
        const int rem = idx - c * 196;
        const int r = rem / 14;
        const int q = rem - r * 14;
        const int h = h0 + r - 3;
        const int w = w0 + q - 3;
        float v = 0.0f;
        if (h >= 0 && h < HW && w >= 0 && w < HW)
            v = xg[(size_t)c * PP + h * HW + w];
        xsm[(c * 14 + r) * 20 + q] = v;
    }
    __syncthreads();

    // ---- involution: thread = (channel c, row). 8 outputs each.
    const int c   = tid >> 3;      // 0..15
    const int row = tid & 7;       // 0..7

    float av[8] = {};
    #pragma unroll 1
    for (int dy = 0; dy < 7; ++dy) {
        float xr[16];
        #pragma unroll
        for (int q4 = 0; q4 < 4; ++q4)
            *(float4*)&xr[q4 * 4] =
                *(const float4*)&xsm[(c * 14 + row + dy) * 20 + q4 * 4];
        #pragma unroll
        for (int dx = 0; dx < 7; ++dx) {
            const int kk = dy * 7 + dx;
            const float4 wa = *(const float4*)&wsm[kk * 68 + row * 8];
            const float4 wb = *(const float4*)&wsm[kk * 68 + row * 8 + 4];
            const float wj[8] = {wa.x, wa.y, wa.z, wa.w, wb.x, wb.y, wb.z, wb.w};
            #pragma unroll
            for (int j = 0; j < 8; ++j)
                av[j] += wj[j] * xr[dx + j];
        }
    }

    float* dst = out + ((size_t)b * C1 + gr * 16 + c) * PP + (h0 + row) * HW + w0;
    *(float4*)&dst[0] = make_float4(av[0], av[1], av[2], av[3]);
    *(float4*)&dst[4] = make_float4(av[4], av[5], av[6], av[7]);
}

// ---------------------------------------------------------------------------
extern "C" void kernel_launch(void* const* d_in, const int* in_sizes, int n_in,
                              void* d_out, int out_size)
{
    const float* x   = (const float*)d_in[0];
    const float* w1  = (const float*)d_in[1];
    const float* g1  = (const float*)d_in[2];
    const float* b1  = (const float*)d_in[3];
    const float* mu1 = (const float*)d_in[4];
    const float* v1  = (const float*)d_in[5];
    const float* ap1 = (const float*)d_in[6];
    const float* ap2 = (const float*)d_in[7];
    const float* ab  = (const float*)d_in[8];
    const float* w2  = (const float*)d_in[9];
    const float* g2  = (const float*)d_in[10];
    const float* b2  = (const float*)d_in[11];
    const float* mu2 = (const float*)d_in[12];
    const float* v2  = (const float*)d_in[13];
    float* out = (float*)d_out;

    k1_conv1_bn_acon<<<NPX / 32, 128>>>(x, w1, g1, b1, mu1, v1, ap1, ap2, ab);

    dim3 grid23(49, 16, BB);
    k23_fused<<<grid23, 128>>>(x, w2, g2, b2, mu2, v2, out);
}